// round 4
// baseline (speedup 1.0000x reference)
#include <cuda_runtime.h>

// GC_3D loss: BCE(mean) + 1 - (1/13) * sum_k [ sum(di_k*dt_k) / (sum(dt_k^2)+1e-5) ]
// Shape (4,1,128,192,192) f32, forward-z canonical offsets.
// R4: packed f32x2 arithmetic (FFMA2) for all diff/accumulate math.

#define DX 192
#define DY 192
#define DZ 128
#define DXY (DX * DY)
#define NX4 48
#define NSUM 27
#define ZCHUNKS 4
#define ZSTEP (DZ / ZCHUNKS)   // 32

typedef unsigned long long u64;

__device__ double g_sums[NSUM];

__global__ void gc3d_zero_kernel() {
    int i = threadIdx.x;
    if (i < NSUM) g_sums[i] = 0.0;
}

// ---- packed f32x2 primitives ----
__device__ __forceinline__ u64 pk2(float lo, float hi) {
    u64 r; asm("mov.b64 %0,{%1,%2};" : "=l"(r) : "f"(lo), "f"(hi)); return r;
}
__device__ __forceinline__ void upk(u64 v, float& lo, float& hi) {
    asm("mov.b64 {%0,%1},%2;" : "=f"(lo), "=f"(hi) : "l"(v));
}
__device__ __forceinline__ u64 fma2(u64 a, u64 b, u64 c) {
    u64 r; asm("fma.rn.f32x2 %0,%1,%2,%3;" : "=l"(r) : "l"(a), "l"(b), "l"(c)); return r;
}
__device__ __forceinline__ u64 mul2(u64 a, u64 b) {
    u64 r; asm("mul.rn.f32x2 %0,%1,%2;" : "=l"(r) : "l"(a), "l"(b)); return r;
}
__device__ __forceinline__ u64 add2(u64 a, u64 b) {
    u64 r; asm("add.rn.f32x2 %0,%1,%2;" : "=l"(r) : "l"(a), "l"(b)); return r;
}
#define NEG1 0xBF800000BF800000ULL   // (-1.0f, -1.0f)
// a - b  ==  fma(b, -1, a)  (single rounding, == sub.rn)
__device__ __forceinline__ u64 sub2(u64 a, u64 b) { return fma2(b, NEG1, a); }

// ---- packed 6-float row windows ----
struct W5 { u64 a01, a12, a23, a34, a45; };
struct W4 { u64 a12, a23, a34, a45; };          // carried center row

__device__ __forceinline__ W5 ldW5(const float* __restrict__ p, int o_m1, int o_p4) {
    float4 v = *reinterpret_cast<const float4*>(p);
    float wm = __ldg(p + o_m1), wp = __ldg(p + o_p4);
    W5 w;
    w.a01 = pk2(wm, v.x); w.a12 = pk2(v.x, v.y); w.a23 = pk2(v.y, v.z);
    w.a34 = pk2(v.z, v.w); w.a45 = pk2(v.w, wp);
    return w;
}

// One (row,dx) offset over 4 voxels: low pair + high pair.
// MA/MB: whether to guard-multiply dt of low/high pair.
template<bool MA, bool MB>
__device__ __forceinline__ void acc2(u64 nIa, u64 nIb, u64 nTa, u64 nTb,
                                     u64 cIa, u64 cIb, u64 cTa, u64 cTb,
                                     u64 Ga, u64 Gb, u64& D, u64& Q)
{
    u64 dia = sub2(nIa, cIa), dib = sub2(nIb, cIb);
    u64 dta = sub2(nTa, cTa), dtb = sub2(nTb, cTb);
    if (MA) dta = mul2(dta, Ga);
    if (MB) dtb = mul2(dtb, Gb);
    D = fma2(dia, dta, D); D = fma2(dib, dtb, D);
    Q = fma2(dta, dta, Q); Q = fma2(dtb, dtb, Q);
}

// Three dx offsets on one row window. GY: row-flag guarded (y-edge path).
// gA0: J0 low guard (fxm [*rf]); gB0: row guard (rf,rf); gB2: J2 high (fxp [*rf]).
template<bool GY>
__device__ __forceinline__ void row3(const W5& Wi, const W5& Wt,
                                     u64 cIa, u64 cIb, u64 cTa, u64 cTb,
                                     u64 gA0, u64 gB0, u64 gB2,
                                     u64* dot, u64* den, int K)
{
    acc2<true, GY >(Wi.a01, Wi.a23, Wt.a01, Wt.a23, cIa, cIb, cTa, cTb, gA0, gB0, dot[K],     den[K]);
    acc2<GY,   GY >(Wi.a12, Wi.a34, Wt.a12, Wt.a34, cIa, cIb, cTa, cTb, gB0, gB0, dot[K + 1], den[K + 1]);
    acc2<GY,   true>(Wi.a23, Wi.a45, Wt.a23, Wt.a45, cIa, cIb, cTa, cTb, gB0, gB2, dot[K + 2], den[K + 2]);
}

// BCE (log2 domain): bce2 += l2 + t*(l1-l2), packed
__device__ __forceinline__ void bce4(u64 cIa, u64 cIb, u64 cTa, u64 cTb, u64& bce2)
{
    float c0, c1, c2, c3;
    upk(cIa, c0, c1); upk(cIb, c2, c3);
    float l10 = __log2f(c0), l11 = __log2f(c1), l12 = __log2f(c2), l13 = __log2f(c3);
    float l20 = __log2f(1.0f - c0), l21 = __log2f(1.0f - c1);
    float l22 = __log2f(1.0f - c2), l23 = __log2f(1.0f - c3);
    u64 l1a = pk2(l10, l11), l1b = pk2(l12, l13);
    u64 l2a = pk2(l20, l21), l2b = pk2(l22, l23);
    bce2 = add2(bce2, l2a); bce2 = fma2(cTa, sub2(l1a, l2a), bce2);
    bce2 = add2(bce2, l2b); bce2 = fma2(cTb, sub2(l1b, l2b), bce2);
}

template<bool YG>
__device__ __forceinline__ void gc3d_march(
    const float* __restrict__ in, const float* __restrict__ tg,
    int base, int nsteps, bool do_epi,
    int o_m1, int o_p4, int dUp, int dDn,
    float fxm, float fxp, float fym, float fyp,
    u64* dot, u64* den, u64& bce2)
{
    // loop-invariant packed guards
    const u64 gxm = pk2(fxm, 1.0f);
    const u64 gxp = pk2(1.0f, fxp);
    // y-edge premultiplied guards (dead code on interior instantiation)
    const u64 gpA0 = pk2(fxm * fyp, fyp), gpB0 = pk2(fyp, fyp), gpB2 = pk2(fyp, fxp * fyp);
    const u64 gmA0 = pk2(fxm * fym, fym), gmB0 = pk2(fym, fym), gmB2 = pk2(fym, fxp * fym);

    W4 CWi, CWt; W5 UWi, UWt;
    {
        W5 c_i = ldW5(in + base, o_m1, o_p4);
        W5 c_t = ldW5(tg + base, o_m1, o_p4);
        CWi.a12 = c_i.a12; CWi.a23 = c_i.a23; CWi.a34 = c_i.a34; CWi.a45 = c_i.a45;
        CWt.a12 = c_t.a12; CWt.a23 = c_t.a23; CWt.a34 = c_t.a34; CWt.a45 = c_t.a45;
    }
    UWi = ldW5(in + base + dUp, o_m1, o_p4);
    UWt = ldW5(tg + base + dUp, o_m1, o_p4);

#pragma unroll 2
    for (int s = 0; s < nsteps; ++s) {
        const int baseN = base + DXY;
        W5 NmI = ldW5(in + baseN + dDn, o_m1, o_p4);
        W5 NmT = ldW5(tg + baseN + dDn, o_m1, o_p4);
        W5 NcI = ldW5(in + baseN,       o_m1, o_p4);
        W5 NcT = ldW5(tg + baseN,       o_m1, o_p4);
        W5 NpI = ldW5(in + baseN + dUp, o_m1, o_p4);
        W5 NpT = ldW5(tg + baseN + dUp, o_m1, o_p4);

        const u64 cIa = CWi.a12, cIb = CWi.a34;
        const u64 cTa = CWt.a12, cTb = CWt.a34;

        bce4(cIa, cIb, cTa, cTb, bce2);

        // k0: (0,0,+1) on center row, J=2 pairs
        acc2<false, true>(CWi.a23, CWi.a45, CWt.a23, CWt.a45,
                          cIa, cIb, cTa, cTb, gxm, gxp, dot[0], den[0]);
        // k1..3: (0,1,dx) carried y+1 row
        row3<YG>(UWi, UWt, cIa, cIb, cTa, cTb,
                 YG ? gpA0 : gxm, gpB0, YG ? gpB2 : gxp, dot, den, 1);
        // k4..6: (1,-1,dx)
        row3<YG>(NmI, NmT, cIa, cIb, cTa, cTb,
                 YG ? gmA0 : gxm, gmB0, YG ? gmB2 : gxp, dot, den, 4);
        // k7..9: (1,0,dx)  (no row guard ever)
        row3<false>(NcI, NcT, cIa, cIb, cTa, cTb, gxm, gmB0, gxp, dot, den, 7);
        // k10..12: (1,1,dx)
        row3<YG>(NpI, NpT, cIa, cIb, cTa, cTb,
                 YG ? gpA0 : gxm, gpB0, YG ? gpB2 : gxp, dot, den, 10);

        CWi.a12 = NcI.a12; CWi.a23 = NcI.a23; CWi.a34 = NcI.a34; CWi.a45 = NcI.a45;
        CWt.a12 = NcT.a12; CWt.a23 = NcT.a23; CWt.a34 = NcT.a34; CWt.a45 = NcT.a45;
        UWi = NpI; UWt = NpT;
        base = baseN;
    }

    if (do_epi) {  // z = 127: only dz=0 offsets, no fresh loads
        const u64 cIa = CWi.a12, cIb = CWi.a34;
        const u64 cTa = CWt.a12, cTb = CWt.a34;
        bce4(cIa, cIb, cTa, cTb, bce2);
        acc2<false, true>(CWi.a23, CWi.a45, CWt.a23, CWt.a45,
                          cIa, cIb, cTa, cTb, gxm, gxp, dot[0], den[0]);
        row3<YG>(UWi, UWt, cIa, cIb, cTa, cTb,
                 YG ? gpA0 : gxm, gpB0, YG ? gpB2 : gxp, dot, den, 1);
    }
}

__global__ void __launch_bounds__(128) gc3d_main_kernel(
    const float* __restrict__ in, const float* __restrict__ tg)
{
    const int tid = blockIdx.x * blockDim.x + threadIdx.x;   // 0..147455
    const int x4 = tid % NX4;
    const int y  = (tid / NX4) % DY;
    const int t2 = tid / (NX4 * DY);   // 0..15
    const int zc = t2 & 3;
    const int b  = t2 >> 2;
    const int z0 = zc * ZSTEP;

    int base = ((b * DZ + z0) * DY + y) * DX + x4 * 4;

    const int   o_m1 = (x4 == 0)       ? 0 : -1;
    const int   o_p4 = (x4 == NX4 - 1) ? 3 : 4;
    const float fxm  = (x4 == 0)       ? 0.0f : 1.0f;
    const float fxp  = (x4 == NX4 - 1) ? 0.0f : 1.0f;
    const int   dUp  = (y == DY - 1) ? 0 : DX;
    const int   dDn  = (y == 0)      ? 0 : -DX;
    const float fyp  = (y == DY - 1) ? 0.0f : 1.0f;
    const float fym  = (y == 0)      ? 0.0f : 1.0f;

    const int  nsteps = (zc == ZCHUNKS - 1) ? (ZSTEP - 1) : ZSTEP;
    const bool do_epi = (zc == ZCHUNKS - 1);

    u64 dot[13], den[13], bce2 = 0ULL;
#pragma unroll
    for (int k = 0; k < 13; ++k) { dot[k] = 0ULL; den[k] = 0ULL; }

    if (y == 0 || y == DY - 1)
        gc3d_march<true >(in, tg, base, nsteps, do_epi, o_m1, o_p4, dUp, dDn,
                          fxm, fxp, fym, fyp, dot, den, bce2);
    else
        gc3d_march<false>(in, tg, base, nsteps, do_epi, o_m1, o_p4, dUp, dDn,
                          fxm, fxp, fym, fyp, dot, den, bce2);

    // unpack lanes, warp butterfly, block reduce, atomic into doubles
    float acc[NSUM];
#pragma unroll
    for (int k = 0; k < 13; ++k) {
        float lo, hi;
        upk(dot[k], lo, hi); acc[k]      = lo + hi;
        upk(den[k], lo, hi); acc[13 + k] = lo + hi;
    }
    { float lo, hi; upk(bce2, lo, hi); acc[26] = lo + hi; }

#pragma unroll
    for (int i = 0; i < NSUM; ++i) {
        float v = acc[i];
#pragma unroll
        for (int o = 16; o > 0; o >>= 1) v += __shfl_xor_sync(0xFFFFFFFFu, v, o);
        acc[i] = v;
    }

    __shared__ float sh[4][NSUM];
    const int wid = threadIdx.x >> 5;
    const int lid = threadIdx.x & 31;
    if (lid == 0) {
#pragma unroll
        for (int i = 0; i < NSUM; ++i) sh[wid][i] = acc[i];
    }
    __syncthreads();
    if (wid == 0 && lid < NSUM) {
        float v = sh[0][lid] + sh[1][lid] + sh[2][lid] + sh[3][lid];
        atomicAdd(&g_sums[lid], (double)v);
    }
}

__global__ void gc3d_finalize_kernel(float* out, double inv_n) {
    if (threadIdx.x == 0 && blockIdx.x == 0) {
        double accv = 0.0;
#pragma unroll
        for (int k = 0; k < 13; ++k)
            accv += g_sums[k] / (g_sums[13 + k] + 1e-5);
        const double bce = -g_sums[26] * inv_n * 0.6931471805599453; // log2 -> ln
        out[0] = (float)(bce + 1.0 - accv / 13.0);
    }
}

extern "C" void kernel_launch(void* const* d_in, const int* in_sizes, int n_in,
                              void* d_out, int out_size)
{
    const float* in = (const float*)d_in[0];
    const float* tg = (const float*)d_in[1];
    float* out = (float*)d_out;
    const int n = in_sizes[0];   // 18874368

    gc3d_zero_kernel<<<1, 32>>>();
    gc3d_main_kernel<<<1152, 128>>>(in, tg);
    gc3d_finalize_kernel<<<1, 32>>>(out, 1.0 / (double)n);
}